// round 6
// baseline (speedup 1.0000x reference)
#include <cuda_runtime.h>
#include <math.h>

#define NN 100000
#define NE 1600000
#define IND 128
#define HID 64

// ---------------- scratch (device globals; no allocation allowed) ----------
// NEVER passed as kernel arguments from host (host shadow + ATS trap) —
// kernels reference these symbols directly.
__device__ float d_xw[(size_t)NN * HID];   // X@W buffer
__device__ float d_agg[(size_t)NN * HID];  // aggregation / h buffer
__device__ float d_dinv[NN];
__device__ int   d_deg[NN];
__device__ float d_g[HID];                 // column sums of h2
__device__ int   d_idx64;                  // 1 if edge_index is int64
__device__ float d_diag0;                  // sampled sum |xw1|
__device__ float d_diag1;                  // sampled sum |h1|

// ---------------- detect edge_index dtype ----------------------------------
__global__ void k_detect(const int* __restrict__ ei) {
    __shared__ int found_nonzero;
    if (threadIdx.x == 0) found_nonzero = 0;
    __syncthreads();
    for (int k = threadIdx.x; k < 4096; k += blockDim.x) {
        if (ei[2 * k + 1] != 0) found_nonzero = 1;  // benign race
    }
    __syncthreads();
    if (threadIdx.x == 0) d_idx64 = found_nonzero ? 0 : 1;
}

// PLANAR layout: src = ei[0..E), dst = ei[E..2E)
__device__ __forceinline__ int edge_src(const void* ei, size_t e, int is64) {
    long long v = is64 ? ((const long long*)ei)[e] : (long long)((const int*)ei)[e];
    return (int)((unsigned long long)v % NN);
}
__device__ __forceinline__ int edge_dst(const void* ei, size_t e, int is64) {
    long long v = is64 ? ((const long long*)ei)[(size_t)NE + e]
                       : (long long)((const int*)ei)[(size_t)NE + e];
    return (int)((unsigned long long)v % NN);
}

// ---------------- init ------------------------------------------------------
__global__ void k_init() {
    int i = blockIdx.x * blockDim.x + threadIdx.x;
    if (i < NN) d_deg[i] = 0;
    if (i < HID) d_g[i] = 0.0f;
    if (i == 0) { d_diag0 = 0.0f; d_diag1 = 0.0f; }
}

__global__ void k_zero_agg() {
    size_t i = (size_t)blockIdx.x * blockDim.x + threadIdx.x;
    size_t total4 = (size_t)NN * HID / 4;
    if (i < total4) reinterpret_cast<float4*>(d_agg)[i] = make_float4(0.f, 0.f, 0.f, 0.f);
}

// ---------------- sampled |.| sum diagnostic (globals referenced inside) ----
__global__ void k_chk(int which) {
    __shared__ float sh[256];
    const float* buf = (which == 0) ? d_xw : d_agg;
    float s = 0.0f;
    for (size_t i = threadIdx.x * 1009; i < (size_t)NN * HID; i += 256 * 1009)
        s += fabsf(buf[i]);
    sh[threadIdx.x] = s;
    __syncthreads();
    for (int off = 128; off > 0; off >>= 1) {
        if (threadIdx.x < off) sh[threadIdx.x] += sh[threadIdx.x + off];
        __syncthreads();
    }
    if (threadIdx.x == 0) {
        if (which == 0) d_diag0 = sh[0]; else d_diag1 = sh[0];
    }
}

// ---------------- degree count ---------------------------------------------
__global__ void k_deg(const void* __restrict__ ei) {
    int e = blockIdx.x * blockDim.x + threadIdx.x;
    int is64 = d_idx64;
    if (e < NE) atomicAdd(&d_deg[edge_dst(ei, e, is64)], 1);
}

__global__ void k_dinv() {
    int i = blockIdx.x * blockDim.x + threadIdx.x;
    if (i < NN) d_dinv[i] = rsqrtf((float)d_deg[i] + 1.0f);
}

// ---------------- GEMM: Y[N,64] = X[N,K] @ W[K,64] -------------------------
// LAYER=1: X = external x, Y = d_xw.  LAYER=2: X = d_agg, Y = d_xw.
template <int K, int LAYER>
__global__ void k_gemm(const float* __restrict__ Xext, const float* __restrict__ W) {
    __shared__ float Ws[K * HID];
    for (int i = threadIdx.x; i < K * HID; i += blockDim.x) Ws[i] = W[i];
    __syncthreads();

    int node = blockIdx.x * blockDim.x + threadIdx.x;
    if (node >= NN) return;

    const float* X = (LAYER == 1) ? Xext : d_agg;
    const float* xr = X + (size_t)node * K;
    float acc[HID];
#pragma unroll
    for (int j = 0; j < HID; j++) acc[j] = 0.0f;

#pragma unroll 4
    for (int k = 0; k < K; k++) {
        float xv = xr[k];
        const float* wrow = &Ws[k * HID];
#pragma unroll
        for (int j = 0; j < HID; j++) acc[j] += xv * wrow[j];
    }

    float4* out = reinterpret_cast<float4*>(d_xw + (size_t)node * HID);
#pragma unroll
    for (int j = 0; j < HID / 4; j++)
        out[j] = make_float4(acc[4 * j], acc[4 * j + 1], acc[4 * j + 2], acc[4 * j + 3]);
}

// ---------------- edge scatter: agg[dst] += xw[src] * dinv[src]*dinv[dst] --
__global__ void k_scatter(const void* __restrict__ ei) {
    size_t t = (size_t)blockIdx.x * blockDim.x + threadIdx.x;
    size_t e = t >> 4;
    if (e >= NE) return;
    int is64 = d_idx64;
    int c = (int)(t & 15) * 4;
    int s = edge_src(ei, e, is64);
    int d = edge_dst(ei, e, is64);
    float coef = d_dinv[s] * d_dinv[d];
    float4 v = *reinterpret_cast<const float4*>(&d_xw[(size_t)s * HID + c]);
    float* o = &d_agg[(size_t)d * HID + c];
    atomicAdd(o + 0, v.x * coef);
    atomicAdd(o + 1, v.y * coef);
    atomicAdd(o + 2, v.z * coef);
    atomicAdd(o + 3, v.w * coef);
}

// ---------------- combine: agg = relu(agg + xw*dinv^2 + b) (in place) ------
__global__ void k_combine(const float* __restrict__ b) {
    size_t i4 = (size_t)blockIdx.x * blockDim.x + threadIdx.x;
    size_t total4 = (size_t)NN * HID / 4;
    if (i4 >= total4) return;
    size_t base = i4 * 4;
    int node = (int)(base / HID);
    int j = (int)(base % HID);
    float di = d_dinv[node];
    float d2 = di * di;
    float4 a = reinterpret_cast<float4*>(d_agg)[i4];
    float4 x = reinterpret_cast<const float4*>(d_xw)[i4];
    a.x = fmaxf(a.x + x.x * d2 + b[j + 0], 0.0f);
    a.y = fmaxf(a.y + x.y * d2 + b[j + 1], 0.0f);
    a.z = fmaxf(a.z + x.z * d2 + b[j + 2], 0.0f);
    a.w = fmaxf(a.w + x.w * d2 + b[j + 3], 0.0f);
    reinterpret_cast<float4*>(d_agg)[i4] = a;
}

// ---------------- combine2 + column reduce into d_g ------------------------
__global__ void k_combine_reduce(const float* __restrict__ b) {
    __shared__ float sh[256];
    int tid = threadIdx.x;
    int j = tid & (HID - 1);
    size_t stride = (size_t)gridDim.x * blockDim.x;
    float bsum = 0.0f;
    float bj = b[j];
    for (size_t i = (size_t)blockIdx.x * blockDim.x + tid; i < (size_t)NN * HID; i += stride) {
        int node = (int)(i / HID);
        float di = d_dinv[node];
        float v = d_agg[i] + d_xw[i] * di * di + bj;
        bsum += fmaxf(v, 0.0f);
    }
    sh[tid] = bsum;
    __syncthreads();
    if (tid < HID) {
        float tot = sh[tid] + sh[tid + 64] + sh[tid + 128] + sh[tid + 192];
        atomicAdd(&d_g[tid], tot);
    }
}

// ---------------- final: sigmoid(mean(h2) @ Wf + bf) + sentinels -----------
__global__ void k_final(const float* __restrict__ Wf, const float* __restrict__ bf,
                        float* __restrict__ out) {
    __shared__ float sh[HID];
    __shared__ float gabs[HID];
    int j = threadIdx.x;
    sh[j]   = d_g[j] * (1.0f / (float)NN) * Wf[j];
    gabs[j] = fabsf(d_g[j]);
    __syncthreads();
    if (j < 32) { sh[j] += sh[j + 32]; gabs[j] += gabs[j + 32]; }
    __syncthreads();
    if (j == 0) {
        float s = 0.0f, ga = 0.0f;
#pragma unroll
        for (int i = 0; i < 32; i++) { s += sh[i]; ga += gabs[i]; }
        float r = 1.0f / (1.0f + expf(-(s + bf[0])));
        if (d_diag0 == 0.0f)      r = 0.11f;   // xw1 dead
        else if (d_diag1 == 0.0f) r = 0.22f;   // h1 dead
        else if (ga == 0.0f)      r = 0.33f;   // g dead
        out[0] = r;
    }
}

extern "C" void kernel_launch(void* const* d_in, const int* in_sizes, int n_in,
                              void* d_out, int out_size) {
    const float* x   = (const float*)d_in[0];
    const void*  ei  = d_in[1];
    const float* W1  = (const float*)d_in[2];
    const float* b1  = (const float*)d_in[3];
    const float* W2  = (const float*)d_in[4];
    const float* b2  = (const float*)d_in[5];
    const float* Wf  = (const float*)d_in[6];
    const float* bf  = (const float*)d_in[7];
    float* out = (float*)d_out;

    const int T = 256;
    int nblk_n   = (NN + T - 1) / T;
    size_t total4 = (size_t)NN * HID / 4;
    int nblk_z   = (int)((total4 + T - 1) / T);
    int nblk_e   = (NE + T - 1) / T;
    int nblk_s   = (int)(((size_t)NE * 16 + T - 1) / T);

    // dtype detection + degrees + init
    k_detect<<<1, 256>>>((const int*)ei);
    k_init<<<nblk_n, T>>>();
    k_deg<<<nblk_e, T>>>(ei);
    k_dinv<<<nblk_n, T>>>();

    // layer 1
    k_gemm<IND, 1><<<(NN + 127) / 128, 128>>>(x, W1);
    k_chk<<<1, 256>>>(0);                  // diag0 = sampled |xw1|
    k_zero_agg<<<nblk_z, T>>>();
    k_scatter<<<nblk_s, T>>>(ei);
    k_combine<<<nblk_z, T>>>(b1);          // d_agg = h1
    k_chk<<<1, 256>>>(1);                  // diag1 = sampled |h1|

    // layer 2
    k_gemm<HID, 2><<<(NN + 127) / 128, 128>>>(nullptr, W2);
    k_zero_agg<<<nblk_z, T>>>();
    k_scatter<<<nblk_s, T>>>(ei);
    k_combine_reduce<<<1024, T>>>(b2);     // sums into d_g

    // readout
    k_final<<<1, HID>>>(Wf, bf, out);
}

// round 7
// speedup vs baseline: 1.4866x; 1.4866x over previous
#include <cuda_runtime.h>
#include <math.h>

#define NN 100000
#define NE 1600000
#define IND 128
#define HID 64

// ---------------- scratch (device globals; never host-passed) ---------------
__device__ float d_xw[(size_t)NN * HID];    // X@W buffer
__device__ float d_agg[(size_t)NN * HID];   // h buffer (gather output)
__device__ float d_dinv[NN];
__device__ int   d_deg[NN];
__device__ int   d_off[NN + 1];             // CSR row offsets (by dst)
__device__ int   d_cursor[NN];              // fill cursors
__device__ int   d_csrc[NE];                // CSR: src node per incoming edge
__device__ float d_g[HID];                  // column sums of h2
__device__ int   d_idx64;

// ---------------- detect edge_index dtype ----------------------------------
__global__ void k_detect(const int* __restrict__ ei) {
    __shared__ int found_nonzero;
    if (threadIdx.x == 0) found_nonzero = 0;
    __syncthreads();
    for (int k = threadIdx.x; k < 4096; k += blockDim.x) {
        if (ei[2 * k + 1] != 0) found_nonzero = 1;
    }
    __syncthreads();
    if (threadIdx.x == 0) d_idx64 = found_nonzero ? 0 : 1;
}

// PLANAR layout: src = ei[0..E), dst = ei[E..2E)
__device__ __forceinline__ int edge_src(const void* ei, size_t e, int is64) {
    long long v = is64 ? ((const long long*)ei)[e] : (long long)((const int*)ei)[e];
    return (int)((unsigned long long)v % NN);
}
__device__ __forceinline__ int edge_dst(const void* ei, size_t e, int is64) {
    long long v = is64 ? ((const long long*)ei)[(size_t)NE + e]
                       : (long long)((const int*)ei)[(size_t)NE + e];
    return (int)((unsigned long long)v % NN);
}

// ---------------- init ------------------------------------------------------
__global__ void k_init() {
    int i = blockIdx.x * blockDim.x + threadIdx.x;
    if (i < NN) d_deg[i] = 0;
    if (i < HID) d_g[i] = 0.0f;
}

// ---------------- degree count ---------------------------------------------
__global__ void k_deg(const void* __restrict__ ei) {
    int e = blockIdx.x * blockDim.x + threadIdx.x;
    int is64 = d_idx64;
    if (e < NE) atomicAdd(&d_deg[edge_dst(ei, e, is64)], 1);
}

__global__ void k_dinv() {
    int i = blockIdx.x * blockDim.x + threadIdx.x;
    if (i < NN) d_dinv[i] = rsqrtf((float)d_deg[i] + 1.0f);
}

// ---------------- single-block exclusive scan of d_deg -> d_off, d_cursor ---
__global__ void k_scan() {
    __shared__ int part[1024];
    const int CH = (NN + 1023) / 1024;      // 98
    int t = threadIdx.x;
    int beg = t * CH, end = min(beg + CH, NN);
    int s = 0;
    for (int i = beg; i < end; i++) s += d_deg[i];
    part[t] = s;
    __syncthreads();
    // inclusive Hillis-Steele scan
    for (int off = 1; off < 1024; off <<= 1) {
        int v = (t >= off) ? part[t - off] : 0;
        __syncthreads();
        part[t] += v;
        __syncthreads();
    }
    int run = (t == 0) ? 0 : part[t - 1];   // exclusive base for this chunk
    for (int i = beg; i < end; i++) {
        d_off[i] = run;
        d_cursor[i] = run;
        run += d_deg[i];
    }
    if (t == 1023) d_off[NN] = run;
}

// ---------------- CSR fill ---------------------------------------------------
__global__ void k_fill(const void* __restrict__ ei) {
    int e = blockIdx.x * blockDim.x + threadIdx.x;
    if (e >= NE) return;
    int is64 = d_idx64;
    int s = edge_src(ei, e, is64);
    int d = edge_dst(ei, e, is64);
    int pos = atomicAdd(&d_cursor[d], 1);
    d_csrc[pos] = s;
}

// ---------------- GEMM: d_xw = X @ W  (X = ext x or d_agg) ------------------
template <int K, int LAYER>
__global__ void k_gemm(const float* __restrict__ Xext, const float* __restrict__ W) {
    __shared__ float Ws[K * HID];
    for (int i = threadIdx.x; i < K * HID; i += blockDim.x) Ws[i] = W[i];
    __syncthreads();

    int node = blockIdx.x * blockDim.x + threadIdx.x;
    if (node >= NN) return;

    const float* X = (LAYER == 1) ? Xext : d_agg;
    const float* xr = X + (size_t)node * K;
    float acc[HID];
#pragma unroll
    for (int j = 0; j < HID; j++) acc[j] = 0.0f;

#pragma unroll 4
    for (int k = 0; k < K; k++) {
        float xv = xr[k];
        const float* wrow = &Ws[k * HID];
#pragma unroll
        for (int j = 0; j < HID; j++) acc[j] += xv * wrow[j];
    }

    float4* out = reinterpret_cast<float4*>(d_xw + (size_t)node * HID);
#pragma unroll
    for (int j = 0; j < HID / 4; j++)
        out[j] = make_float4(acc[4 * j], acc[4 * j + 1], acc[4 * j + 2], acc[4 * j + 3]);
}

// ---------------- gather: d_agg[n] = relu(dinv[n]*sum_{s->n} dinv[s]*xw[s]
//                                          + dinv[n]^2*xw[n] + b) ------------
// 16 lanes per node, one float4 (4 columns) per lane.
__global__ void k_gather(const float* __restrict__ bias) {
    int node = blockIdx.x * (blockDim.x >> 4) + (threadIdx.x >> 4);
    int lane = threadIdx.x & 15;
    if (node >= NN) return;

    int beg = d_off[node], end = d_off[node + 1];
    float4 acc = make_float4(0.f, 0.f, 0.f, 0.f);
    for (int k = beg; k < end; k++) {
        int s = d_csrc[k];                       // L1-broadcast across 16 lanes
        float ds = d_dinv[s];
        float4 v = *reinterpret_cast<const float4*>(&d_xw[(size_t)s * HID + lane * 4]);
        acc.x += ds * v.x; acc.y += ds * v.y; acc.z += ds * v.z; acc.w += ds * v.w;
    }
    float dd = d_dinv[node];
    float d2 = dd * dd;
    float4 self = *reinterpret_cast<const float4*>(&d_xw[(size_t)node * HID + lane * 4]);
    const float* b = bias + lane * 4;
    float4 r;
    r.x = fmaxf(acc.x * dd + self.x * d2 + b[0], 0.0f);
    r.y = fmaxf(acc.y * dd + self.y * d2 + b[1], 0.0f);
    r.z = fmaxf(acc.z * dd + self.z * d2 + b[2], 0.0f);
    r.w = fmaxf(acc.w * dd + self.w * d2 + b[3], 0.0f);
    *reinterpret_cast<float4*>(&d_agg[(size_t)node * HID + lane * 4]) = r;
}

// ---------------- column reduce of d_agg into d_g ---------------------------
__global__ void k_reduce() {
    __shared__ float sh[256];
    int tid = threadIdx.x;
    size_t stride = (size_t)gridDim.x * blockDim.x;   // multiple of 64
    float bsum = 0.0f;
    for (size_t i = (size_t)blockIdx.x * blockDim.x + tid; i < (size_t)NN * HID; i += stride)
        bsum += d_agg[i];
    sh[tid] = bsum;
    __syncthreads();
    if (tid < HID) {
        float tot = sh[tid] + sh[tid + 64] + sh[tid + 128] + sh[tid + 192];
        atomicAdd(&d_g[tid], tot);
    }
}

// ---------------- final: sigmoid(mean(h2) @ Wf + bf) ------------------------
__global__ void k_final(const float* __restrict__ Wf, const float* __restrict__ bf,
                        float* __restrict__ out) {
    __shared__ float sh[HID];
    int j = threadIdx.x;
    sh[j] = d_g[j] * (1.0f / (float)NN) * Wf[j];
    __syncthreads();
    if (j < 32) sh[j] += sh[j + 32];
    __syncthreads();
    if (j == 0) {
        float s = 0.0f;
#pragma unroll
        for (int i = 0; i < 32; i++) s += sh[i];
        out[0] = 1.0f / (1.0f + expf(-(s + bf[0])));
    }
}

extern "C" void kernel_launch(void* const* d_in, const int* in_sizes, int n_in,
                              void* d_out, int out_size) {
    const float* x   = (const float*)d_in[0];
    const void*  ei  = d_in[1];
    const float* W1  = (const float*)d_in[2];
    const float* b1  = (const float*)d_in[3];
    const float* W2  = (const float*)d_in[4];
    const float* b2  = (const float*)d_in[5];
    const float* Wf  = (const float*)d_in[6];
    const float* bf  = (const float*)d_in[7];
    float* out = (float*)d_out;

    const int T = 256;
    int nblk_n = (NN + T - 1) / T;
    int nblk_e = (NE + T - 1) / T;
    int nblk_g = (NN * 16 + T - 1) / T;    // gather: 16 lanes/node

    // graph prep
    k_detect<<<1, 256>>>((const int*)ei);
    k_init<<<nblk_n, T>>>();
    k_deg<<<nblk_e, T>>>(ei);
    k_dinv<<<nblk_n, T>>>();
    k_scan<<<1, 1024>>>();
    k_fill<<<nblk_e, T>>>(ei);

    // layer 1
    k_gemm<IND, 1><<<(NN + 127) / 128, 128>>>(x, W1);
    k_gather<<<nblk_g, T>>>(b1);           // d_agg = h1 (bias+relu fused)

    // layer 2
    k_gemm<HID, 2><<<(NN + 127) / 128, 128>>>(nullptr, W2);
    k_gather<<<nblk_g, T>>>(b2);           // d_agg = h2

    // readout
    k_reduce<<<1024, T>>>();
    k_final<<<1, HID>>>(Wf, bf, out);
}